// round 1
// baseline (speedup 1.0000x reference)
#include <cuda_runtime.h>
#include <math.h>

#define NB    2        // batch
#define CIN   320      // input channels
#define COUT  160      // F_int
#define S_TOT 131072   // 32*64*64 spatial

// Scratch (device globals; no allocations allowed)
__device__ float d_y[2][(size_t)NB * COUT * S_TOT];   // conv0 = Wg*g+bg, conv1 = Wx*x+bx
__device__ float d_sum[2 * NB * COUT];
__device__ float d_sumsq[2 * NB * COUT];
__device__ float d_mu[2 * NB * COUT];
__device__ float d_istd[2 * NB * COUT];

// ---------------------------------------------------------------------------
__global__ void zero_stats() {
    int i = blockIdx.x * blockDim.x + threadIdx.x;
    if (i < 2 * NB * COUT) { d_sum[i] = 0.f; d_sumsq[i] = 0.f; }
}

// ---------------------------------------------------------------------------
// C[co, s] = sum_ci W[co,ci] * X[ci,s] + bias[co], fused per-(n,co) sum/sumsq
constexpr int BM = 80;   // output-channel tile
constexpr int BN = 64;   // spatial tile
constexpr int BK = 16;   // k tile

__global__ __launch_bounds__(256)
void gemm_stats(const float* __restrict__ X, const float* __restrict__ W,
                const float* __restrict__ bias, int conv)
{
    const int n   = blockIdx.z;
    const int co0 = blockIdx.y * BM;
    const int s0  = blockIdx.x * BN;
    const float* Xn = X + (size_t)n * CIN * S_TOT;
    float*       Yn = d_y[conv] + (size_t)n * COUT * S_TOT;

    __shared__ float As[BK][BM];
    __shared__ float Bs[BK][BN];

    const int t  = threadIdx.x;
    const int tx = t & 15;    // spatial sub-index
    const int ty = t >> 4;    // channel sub-index

    float acc[5][4];
#pragma unroll
    for (int i = 0; i < 5; i++)
#pragma unroll
        for (int j = 0; j < 4; j++) acc[i][j] = 0.f;

    for (int k0 = 0; k0 < CIN; k0 += BK) {
        __syncthreads();
        // A tile: 80 x 16 (stored transposed As[k][m])
#pragma unroll
        for (int i = 0; i < 5; i++) {
            int idx = t + i * 256;
            int m = idx >> 4, k = idx & 15;
            As[k][m] = W[(size_t)(co0 + m) * CIN + k0 + k];
        }
        // B tile: 16 x 64, coalesced rows
#pragma unroll
        for (int i = 0; i < 4; i++) {
            int k  = (t >> 6) + i * 4;
            int sn = t & 63;
            Bs[k][sn] = Xn[(size_t)(k0 + k) * S_TOT + s0 + sn];
        }
        __syncthreads();
#pragma unroll
        for (int k = 0; k < BK; k++) {
            float a[5], b[4];
#pragma unroll
            for (int i = 0; i < 5; i++) a[i] = As[k][ty + 16 * i];
#pragma unroll
            for (int j = 0; j < 4; j++) b[j] = Bs[k][tx + 16 * j];
#pragma unroll
            for (int i = 0; i < 5; i++)
#pragma unroll
                for (int j = 0; j < 4; j++) acc[i][j] = fmaf(a[i], b[j], acc[i][j]);
        }
    }

    // Epilogue: +bias, store Y, warp-reduce sum/sumsq over the 16 tx lanes
#pragma unroll
    for (int i = 0; i < 5; i++) {
        int co = co0 + ty + 16 * i;
        float bv = bias[co];
        float s_ = 0.f, s2 = 0.f;
#pragma unroll
        for (int j = 0; j < 4; j++) {
            float v = acc[i][j] + bv;
            Yn[(size_t)co * S_TOT + s0 + tx + 16 * j] = v;
            s_ += v;
            s2 = fmaf(v, v, s2);
        }
#pragma unroll
        for (int off = 1; off < 16; off <<= 1) {
            s_ += __shfl_xor_sync(0xffffffffu, s_, off);
            s2 += __shfl_xor_sync(0xffffffffu, s2, off);
        }
        if (tx == 0) {
            atomicAdd(&d_sum  [conv * NB * COUT + n * COUT + co], s_);
            atomicAdd(&d_sumsq[conv * NB * COUT + n * COUT + co], s2);
        }
    }
}

// ---------------------------------------------------------------------------
__global__ void finalize_stats() {
    int i = blockIdx.x * blockDim.x + threadIdx.x;
    if (i < 2 * NB * COUT) {
        float m   = d_sum[i] * (1.f / (float)S_TOT);
        float var = d_sumsq[i] * (1.f / (float)S_TOT) - m * m;
        d_mu[i]   = m;
        d_istd[i] = rsqrtf(var + 1e-5f);
    }
}

// ---------------------------------------------------------------------------
// Fused: normalize both branches, ELU, sum, Wpsi-dot, sigmoid, out = x * psi
__global__ __launch_bounds__(256)
void fuse_gate(const float* __restrict__ x, const float* __restrict__ Wpsi,
               const float* __restrict__ bpsi, float* __restrict__ out)
{
    __shared__ float smug[COUT], ssig[COUT], smux[COUT], ssix[COUT], sw[COUT];
    const int n   = blockIdx.y;
    const int tid = threadIdx.x;
    if (tid < COUT) {
        smug[tid] = d_mu  [n * COUT + tid];
        ssig[tid] = d_istd[n * COUT + tid];
        smux[tid] = d_mu  [(NB + n) * COUT + tid];
        ssix[tid] = d_istd[(NB + n) * COUT + tid];
        sw[tid]   = Wpsi[tid];
    }
    __syncthreads();

    const size_t s  = (size_t)blockIdx.x * 256 + tid;
    const float* yg = d_y[0] + (size_t)n * COUT * S_TOT + s;
    const float* yx = d_y[1] + (size_t)n * COUT * S_TOT + s;
    const float* xn = x      + (size_t)n * CIN  * S_TOT + s;
    float*       on = out    + (size_t)n * CIN  * S_TOT + s;

    float acc = bpsi[0];
#pragma unroll 8
    for (int c = 0; c < COUT; c++) {
        float a = (yg[(size_t)c * S_TOT] - smug[c]) * ssig[c];
        a = a > 0.f ? a : (__expf(a) - 1.f);
        float b = (yx[(size_t)c * S_TOT] - smux[c]) * ssix[c];
        b = b > 0.f ? b : (__expf(b) - 1.f);
        acc = fmaf(sw[c], a + b, acc);
    }
    const float psi = 1.f / (1.f + __expf(-acc));

#pragma unroll 8
    for (int c = 0; c < CIN; c++)
        on[(size_t)c * S_TOT] = xn[(size_t)c * S_TOT] * psi;
}

// ---------------------------------------------------------------------------
extern "C" void kernel_launch(void* const* d_in, const int* in_sizes, int n_in,
                              void* d_out, int out_size)
{
    const float* g    = (const float*)d_in[0];
    const float* x    = (const float*)d_in[1];
    const float* Wg   = (const float*)d_in[2];
    const float* bg   = (const float*)d_in[3];
    const float* Wx   = (const float*)d_in[4];
    const float* bx   = (const float*)d_in[5];
    const float* Wpsi = (const float*)d_in[6];
    const float* bpsi = (const float*)d_in[7];
    float* out = (float*)d_out;

    zero_stats<<<2, 512>>>();

    dim3 gg(S_TOT / BN, COUT / BM, NB);   // (2048, 2, 2)
    gemm_stats<<<gg, 256>>>(g, Wg, bg, 0);
    gemm_stats<<<gg, 256>>>(x, Wx, bx, 1);

    finalize_stats<<<2, 512>>>();

    dim3 gf(S_TOT / 256, NB);             // (512, 2)
    fuse_gate<<<gf, 256>>>(x, Wpsi, bpsi, out);
}

// round 3
// speedup vs baseline: 2.2079x; 2.2079x over previous
#include <cuda_runtime.h>
#include <cuda_bf16.h>
#include <cstdint>
#include <math.h>

#define NB    2
#define CIN   320
#define COUT  160
#define S_TOT 131072
#define BM    128          // spatial tile
#define BK    32           // k chunk
#define NCHUNK (CIN / BK)  // 10

// ---------------- scratch (device globals) ---------------------------------
__device__ float d_y[2][(size_t)NB * COUT * S_TOT];   // [conv][n][co][s]
__device__ float d_sum[2 * NB * COUT];
__device__ float d_sumsq[2 * NB * COUT];
__device__ float d_mu[2 * NB * COUT];
__device__ float d_istd[2 * NB * COUT];
// prepacked W: per (conv,chunk): hi[160*80B] | lo[160*80B]  (padded smem image)
#define WPACK_PER 25600
__device__ __align__(16) unsigned char d_Wpack[2 * NCHUNK * WPACK_PER];

// ---------------- helpers ---------------------------------------------------
__device__ __forceinline__ uint32_t smem_u32(const void* p) {
    uint32_t a;
    asm("{ .reg .u64 t; cvta.to.shared.u64 t, %1; cvt.u32.u64 %0, t; }" : "=r"(a) : "l"(p));
    return a;
}
__device__ __forceinline__ void ldsm_x4(uint32_t* r, uint32_t addr) {
    asm volatile("ldmatrix.sync.aligned.m8n8.x4.shared.b16 {%0,%1,%2,%3}, [%4];"
                 : "=r"(r[0]), "=r"(r[1]), "=r"(r[2]), "=r"(r[3]) : "r"(addr));
}
__device__ __forceinline__ void mma16816(float* d, const uint32_t* a, const uint32_t* b) {
    asm volatile("mma.sync.aligned.m16n8k16.row.col.f32.bf16.bf16.f32 "
                 "{%0,%1,%2,%3}, {%4,%5,%6,%7}, {%8,%9}, {%0,%1,%2,%3};"
                 : "+f"(d[0]), "+f"(d[1]), "+f"(d[2]), "+f"(d[3])
                 : "r"(a[0]), "r"(a[1]), "r"(a[2]), "r"(a[3]), "r"(b[0]), "r"(b[1]));
}
__device__ __forceinline__ uint32_t pack_hi(float v0, float v1, uint32_t& lo) {
    __nv_bfloat16 h0 = __float2bfloat16(v0);
    __nv_bfloat16 h1 = __float2bfloat16(v1);
    float r0 = v0 - __bfloat162float(h0);
    float r1 = v1 - __bfloat162float(h1);
    __nv_bfloat162 L = __halves2bfloat162(__float2bfloat16(r0), __float2bfloat16(r1));
    lo = *(uint32_t*)&L;
    __nv_bfloat162 H = __halves2bfloat162(h0, h1);
    return *(uint32_t*)&H;
}

// smem layout (bytes): A rows 80B (32 bf16 + 16B pad), B rows 80B
#define AHI_OFF 0
#define ALO_OFF 10240
#define BHI_OFF 20480
#define BLO_OFF 33280
#define SMEM_BYTES 46080

// ---------------------------------------------------------------------------
__global__ void zero_stats() {
    int i = blockIdx.x * blockDim.x + threadIdx.x;
    if (i < 2 * NB * COUT) { d_sum[i] = 0.f; d_sumsq[i] = 0.f; }
}

// Pack Wg/Wx into padded bf16 hi/lo smem images
__global__ void prepack_W(const float* __restrict__ Wg, const float* __restrict__ Wx) {
    int i = blockIdx.x * blockDim.x + threadIdx.x;
    if (i >= 2 * NCHUNK * COUT * 20) return;
    int conv  = i / (NCHUNK * COUT * 20);
    int r     = i % (NCHUNK * COUT * 20);
    int chunk = r / (COUT * 20);
    int r2    = r % (COUT * 20);
    int co    = r2 / 20;
    int wp    = r2 % 20;           // 4-byte word within 80B row
    float v0 = 0.f, v1 = 0.f;
    if (wp < 16) {
        const float* W = conv ? Wx : Wg;
        int k = chunk * BK + 2 * wp;
        v0 = W[co * CIN + k];
        v1 = W[co * CIN + k + 1];
    }
    uint32_t lo, hi = pack_hi(v0, v1, lo);
    size_t base = (size_t)(conv * NCHUNK + chunk) * WPACK_PER;
    *(uint32_t*)(d_Wpack + base + co * 80 + wp * 4)         = hi;
    *(uint32_t*)(d_Wpack + base + 12800 + co * 80 + wp * 4) = lo;
}

// ---------------------------------------------------------------------------
// mma.sync GEMM: y[co, s] = sum_ci W[co,ci] X[ci,s] + bias, fused stats
__global__ __launch_bounds__(256, 1)
void gemm_mma(const float* __restrict__ X, const float* __restrict__ bias, int conv)
{
    __shared__ __align__(16) unsigned char smem_[SMEM_BYTES];
    const uint32_t sb = smem_u32(smem_);

    const int tid  = threadIdx.x;
    const int lane = tid & 31;
    const int warp = tid >> 5;
    const int wm   = warp & 3;   // 4 warps along M (32 rows each)
    const int wn   = warp >> 2;  // 2 warps along N (80 cols each)
    const int n    = blockIdx.y;
    const int s0   = blockIdx.x * BM;
    const float* Xn = X + (size_t)n * CIN * S_TOT;

    float acc[2][10][4];
#pragma unroll
    for (int mt = 0; mt < 2; mt++)
#pragma unroll
        for (int nt = 0; nt < 10; nt++)
#pragma unroll
            for (int q = 0; q < 4; q++) acc[mt][nt][q] = 0.f;

    for (int c = 0; c < NCHUNK; c++) {
        __syncthreads();
        // ---- B fill: straight copy of prepacked image (hi+lo contiguous 25600B)
        {
            const float4* src = (const float4*)(d_Wpack + (size_t)(conv * NCHUNK + c) * WPACK_PER);
            float4* dst = (float4*)(smem_ + BHI_OFF);
#pragma unroll
            for (int i = 0; i < 7; i++) {
                int idx = tid + i * 256;
                if (idx < 1600) dst[idx] = src[idx];
            }
        }
        // ---- A fill: read X[k][s] coalesced, convert+transpose into [s][k]
#pragma unroll
        for (int it = 0; it < 2; it++) {
            int t    = tid + it * 256;
            int sloc = t & 127;
            int kb   = t >> 7;        // k-block of 8
            const float* src = Xn + (size_t)(c * BK + kb * 8) * S_TOT + s0 + sloc;
            float v[8];
#pragma unroll
            for (int j = 0; j < 8; j++) v[j] = src[(size_t)j * S_TOT];
            uint32_t hw[4], lw[4];
#pragma unroll
            for (int j = 0; j < 4; j++) hw[j] = pack_hi(v[2 * j], v[2 * j + 1], lw[j]);
            uint32_t off = sloc * 80 + kb * 16;
            *(uint4*)(smem_ + AHI_OFF + off) = make_uint4(hw[0], hw[1], hw[2], hw[3]);
            *(uint4*)(smem_ + ALO_OFF + off) = make_uint4(lw[0], lw[1], lw[2], lw[3]);
        }
        __syncthreads();

        // ---- compute: 2 k-steps of k16
#pragma unroll
        for (int ks = 0; ks < 2; ks++) {
            uint32_t aH[2][4], aL[2][4];
            const uint32_t arow = wm * 32 + (lane & 15);
            const uint32_t acol = ks * 32 + (lane >> 4) * 16;
#pragma unroll
            for (int mt = 0; mt < 2; mt++) {
                uint32_t addr = (arow + mt * 16) * 80 + acol;
                ldsm_x4(aH[mt], sb + AHI_OFF + addr);
                ldsm_x4(aL[mt], sb + ALO_OFF + addr);
            }
            const uint32_t brow0 = wn * 80 + (lane >> 4) * 8 + (lane & 7);
            const uint32_t bcol  = ks * 32 + ((lane >> 3) & 1) * 16;
#pragma unroll
            for (int p = 0; p < 5; p++) {   // pairs of n-tiles
                uint32_t bH[4], bL[4];
                uint32_t addr = (brow0 + p * 16) * 80 + bcol;
                ldsm_x4(bH, sb + BHI_OFF + addr);
                ldsm_x4(bL, sb + BLO_OFF + addr);
#pragma unroll
                for (int h = 0; h < 2; h++) {
                    int nt = 2 * p + h;
#pragma unroll
                    for (int mt = 0; mt < 2; mt++) {
                        mma16816(acc[mt][nt], aH[mt], bH + 2 * h);
                        mma16816(acc[mt][nt], aL[mt], bH + 2 * h);
                        mma16816(acc[mt][nt], aH[mt], bL + 2 * h);
                    }
                }
            }
        }
    }

    // ---- epilogue: +bias, store y[co][s], per-co sum/sumsq atomics
    float* ybase = d_y[conv] + (size_t)n * COUT * S_TOT;
    const int statbase = conv * NB * COUT + n * COUT;
    const int r0 = s0 + wm * 32 + (lane >> 2);
#pragma unroll
    for (int nt = 0; nt < 10; nt++) {
        int co0 = wn * 80 + nt * 8 + 2 * (lane & 3);
        float b0 = bias[co0], b1 = bias[co0 + 1];
        float sA = 0.f, qA = 0.f, sB = 0.f, qB = 0.f;
#pragma unroll
        for (int mt = 0; mt < 2; mt++) {
            float c0 = acc[mt][nt][0] + b0;
            float c1 = acc[mt][nt][1] + b1;
            float c2 = acc[mt][nt][2] + b0;
            float c3 = acc[mt][nt][3] + b1;
            int r = r0 + mt * 16;
            ybase[(size_t)co0 * S_TOT + r]           = c0;
            ybase[(size_t)(co0 + 1) * S_TOT + r]     = c1;
            ybase[(size_t)co0 * S_TOT + r + 8]       = c2;
            ybase[(size_t)(co0 + 1) * S_TOT + r + 8] = c3;
            sA += c0 + c2; qA += c0 * c0 + c2 * c2;
            sB += c1 + c3; qB += c1 * c1 + c3 * c3;
        }
#pragma unroll
        for (int o = 4; o < 32; o <<= 1) {
            sA += __shfl_xor_sync(0xffffffffu, sA, o);
            qA += __shfl_xor_sync(0xffffffffu, qA, o);
            sB += __shfl_xor_sync(0xffffffffu, sB, o);
            qB += __shfl_xor_sync(0xffffffffu, qB, o);
        }
        if (lane < 4) {
            atomicAdd(&d_sum[statbase + co0], sA);
            atomicAdd(&d_sumsq[statbase + co0], qA);
            atomicAdd(&d_sum[statbase + co0 + 1], sB);
            atomicAdd(&d_sumsq[statbase + co0 + 1], qB);
        }
    }
}

// ---------------------------------------------------------------------------
__global__ void finalize_stats() {
    int i = blockIdx.x * blockDim.x + threadIdx.x;
    if (i < 2 * NB * COUT) {
        float m   = d_sum[i] * (1.f / (float)S_TOT);
        float var = d_sumsq[i] * (1.f / (float)S_TOT) - m * m;
        d_mu[i]   = m;
        d_istd[i] = rsqrtf(var + 1e-5f);
    }
}

// ---------------------------------------------------------------------------
// Fused: normalize both branches, ELU, sum, Wpsi-dot, sigmoid, out = x * psi
__global__ __launch_bounds__(256)
void fuse_gate(const float* __restrict__ x, const float* __restrict__ Wpsi,
               const float* __restrict__ bpsi, float* __restrict__ out)
{
    __shared__ float smug[COUT], ssig[COUT], smux[COUT], ssix[COUT], sw[COUT];
    const int n = blockIdx.y, tid = threadIdx.x;
    if (tid < COUT) {
        smug[tid] = d_mu[n * COUT + tid];
        ssig[tid] = d_istd[n * COUT + tid];
        smux[tid] = d_mu[(NB + n) * COUT + tid];
        ssix[tid] = d_istd[(NB + n) * COUT + tid];
        sw[tid]   = Wpsi[tid];
    }
    __syncthreads();

    const size_t s  = (size_t)blockIdx.x * 256 + tid;
    const float* yg = d_y[0] + (size_t)n * COUT * S_TOT + s;
    const float* yx = d_y[1] + (size_t)n * COUT * S_TOT + s;
    const float* xn = x      + (size_t)n * CIN  * S_TOT + s;
    float*       on = out    + (size_t)n * CIN  * S_TOT + s;

    float acc = bpsi[0];
#pragma unroll 8
    for (int c = 0; c < COUT; c++) {
        float a = (yg[(size_t)c * S_TOT] - smug[c]) * ssig[c];
        a = a > 0.f ? a : (__expf(a) - 1.f);
        float b = (yx[(size_t)c * S_TOT] - smux[c]) * ssix[c];
        b = b > 0.f ? b : (__expf(b) - 1.f);
        acc = fmaf(sw[c], a + b, acc);
    }
    const float psi = 1.f / (1.f + __expf(-acc));

#pragma unroll 8
    for (int c = 0; c < CIN; c++)
        on[(size_t)c * S_TOT] = xn[(size_t)c * S_TOT] * psi;
}

// ---------------------------------------------------------------------------
extern "C" void kernel_launch(void* const* d_in, const int* in_sizes, int n_in,
                              void* d_out, int out_size)
{
    const float* g    = (const float*)d_in[0];
    const float* x    = (const float*)d_in[1];
    const float* Wg   = (const float*)d_in[2];
    const float* bg   = (const float*)d_in[3];
    const float* Wx   = (const float*)d_in[4];
    const float* bx   = (const float*)d_in[5];
    const float* Wpsi = (const float*)d_in[6];
    const float* bpsi = (const float*)d_in[7];
    float* out = (float*)d_out;

    prepack_W<<<(2 * NCHUNK * COUT * 20 + 255) / 256, 256>>>(Wg, Wx);
    zero_stats<<<2, 512>>>();

    dim3 gg(S_TOT / BM, NB);   // (1024, 2)
    gemm_mma<<<gg, 256>>>(g, bg, 0);
    gemm_mma<<<gg, 256>>>(x, bx, 1);

    finalize_stats<<<2, 512>>>();

    dim3 gf(S_TOT / 256, NB);  // (512, 2)
    fuse_gate<<<gf, 256>>>(x, Wpsi, bpsi, out);
}

// round 5
// speedup vs baseline: 3.3723x; 1.5274x over previous
#include <cuda_runtime.h>
#include <cuda_bf16.h>
#include <cstdint>
#include <math.h>

#define NB    2
#define CIN   320
#define COUT  160
#define S_TOT 131072
#define BM    64           // spatial tile per CTA
#define BK    32           // k chunk
#define NCHUNK (CIN / BK)  // 10

// ---------------- scratch (device globals) ---------------------------------
__device__ float d_y[2][(size_t)NB * COUT * S_TOT];   // [conv][n][co][s]
__device__ float d_sum[2 * NB * COUT];
__device__ float d_sumsq[2 * NB * COUT];
__device__ float d_mu[2 * NB * COUT];
__device__ float d_istd[2 * NB * COUT];
// prepacked W: per (conv,chunk): hi[160*80B] | lo[160*80B] (padded smem image)
#define WPACK_PER 25600
__device__ __align__(16) unsigned char d_Wpack[2 * NCHUNK * WPACK_PER];

// ---------------- helpers ---------------------------------------------------
__device__ __forceinline__ uint32_t smem_u32(const void* p) {
    uint32_t a;
    asm("{ .reg .u64 t; cvta.to.shared.u64 t, %1; cvt.u32.u64 %0, t; }" : "=r"(a) : "l"(p));
    return a;
}
__device__ __forceinline__ void ldsm_x4(uint32_t* r, uint32_t addr) {
    asm volatile("ldmatrix.sync.aligned.m8n8.x4.shared.b16 {%0,%1,%2,%3}, [%4];"
                 : "=r"(r[0]), "=r"(r[1]), "=r"(r[2]), "=r"(r[3]) : "r"(addr));
}
__device__ __forceinline__ void ldsm_x2(uint32_t* r, uint32_t addr) {
    asm volatile("ldmatrix.sync.aligned.m8n8.x2.shared.b16 {%0,%1}, [%2];"
                 : "=r"(r[0]), "=r"(r[1]) : "r"(addr));
}
__device__ __forceinline__ void mma16816(float* d, const uint32_t* a, const uint32_t* b) {
    asm volatile("mma.sync.aligned.m16n8k16.row.col.f32.bf16.bf16.f32 "
                 "{%0,%1,%2,%3}, {%4,%5,%6,%7}, {%8,%9}, {%0,%1,%2,%3};"
                 : "+f"(d[0]), "+f"(d[1]), "+f"(d[2]), "+f"(d[3])
                 : "r"(a[0]), "r"(a[1]), "r"(a[2]), "r"(a[3]), "r"(b[0]), "r"(b[1]));
}
__device__ __forceinline__ uint32_t pack_hi(float v0, float v1, uint32_t& lo) {
    __nv_bfloat16 h0 = __float2bfloat16(v0);
    __nv_bfloat16 h1 = __float2bfloat16(v1);
    float r0 = v0 - __bfloat162float(h0);
    float r1 = v1 - __bfloat162float(h1);
    __nv_bfloat162 L = __halves2bfloat162(__float2bfloat16(r0), __float2bfloat16(r1));
    lo = *(uint32_t*)&L;
    __nv_bfloat162 H = __halves2bfloat162(h0, h1);
    return *(uint32_t*)&H;
}
__device__ __forceinline__ void cp_async16(uint32_t saddr, const void* g) {
    asm volatile("cp.async.cg.shared.global [%0], [%1], 16;" :: "r"(saddr), "l"(g) : "memory");
}
#define CP_COMMIT() asm volatile("cp.async.commit_group;" ::: "memory")
#define CP_WAIT0()  asm volatile("cp.async.wait_group 0;" ::: "memory")

// smem layout (dynamic): A hi[64*80] | A lo[64*80] | Bbuf0[25600] | Bbuf1[25600]
#define AHI_OFF 0
#define ALO_OFF 5120
#define B0_OFF  10240
#define B1_OFF  35840
#define SMEM_BYTES 61440
#define BLO_REL 12800   // lo block inside a B buffer

// ---------------------------------------------------------------------------
__global__ void zero_stats() {
    int i = blockIdx.x * blockDim.x + threadIdx.x;
    if (i < 2 * NB * COUT) { d_sum[i] = 0.f; d_sumsq[i] = 0.f; }
}

// Pack Wg/Wx into padded bf16 hi/lo smem images
__global__ void prepack_W(const float* __restrict__ Wg, const float* __restrict__ Wx) {
    int i = blockIdx.x * blockDim.x + threadIdx.x;
    if (i >= 2 * NCHUNK * COUT * 20) return;
    int conv  = i / (NCHUNK * COUT * 20);
    int r     = i % (NCHUNK * COUT * 20);
    int chunk = r / (COUT * 20);
    int r2    = r % (COUT * 20);
    int co    = r2 / 20;
    int wp    = r2 % 20;           // 4-byte word within 80B row
    float v0 = 0.f, v1 = 0.f;
    if (wp < 16) {
        const float* W = conv ? Wx : Wg;
        int k = chunk * BK + 2 * wp;
        v0 = W[co * CIN + k];
        v1 = W[co * CIN + k + 1];
    }
    uint32_t lo, hi = pack_hi(v0, v1, lo);
    size_t base = (size_t)(conv * NCHUNK + chunk) * WPACK_PER;
    *(uint32_t*)(d_Wpack + base + co * 80 + wp * 4)           = hi;
    *(uint32_t*)(d_Wpack + base + BLO_REL + co * 80 + wp * 4) = lo;
}

// ---------------------------------------------------------------------------
// mma.sync GEMM, CTA tile 64x160, 2 CTAs/SM, cp.async-pipelined B, reg-prefetch A
__global__ __launch_bounds__(256, 2)
void gemm_mma(const float* __restrict__ X, const float* __restrict__ bias, int conv)
{
    extern __shared__ __align__(16) unsigned char smem_[];
    const uint32_t sb = smem_u32(smem_);

    const int tid  = threadIdx.x;
    const int lane = tid & 31;
    const int warp = tid >> 5;
    const int wm   = warp & 1;   // 2 warps along M (32 rows each)
    const int wn   = warp >> 1;  // 4 warps along N (40 cols each)
    const int n    = blockIdx.y;
    const int s0   = blockIdx.x * BM;
    const float* Xn = X + (size_t)n * CIN * S_TOT;
    const unsigned char* Wb = d_Wpack + (size_t)conv * NCHUNK * WPACK_PER;

    // A prefetch coords: each thread: 8 consecutive k rows at one s
    const int sloc = tid & 63;
    const int kb   = tid >> 6;   // 0..3 (blocks of 8 k)
    const float* asrc0 = Xn + (size_t)(kb * 8) * S_TOT + s0 + sloc;

    float acc[2][5][4];
#pragma unroll
    for (int mt = 0; mt < 2; mt++)
#pragma unroll
        for (int nt = 0; nt < 5; nt++)
#pragma unroll
            for (int q = 0; q < 4; q++) acc[mt][nt][q] = 0.f;

    // ---- prologue: prefetch chunk 0
    float v[8];
#pragma unroll
    for (int j = 0; j < 8; j++) v[j] = asrc0[(size_t)j * S_TOT];
    {
        const unsigned char* src = Wb;
#pragma unroll
        for (int i = 0; i < 7; i++) {
            int idx = tid + i * 256;
            if (idx < 1600) cp_async16(sb + B0_OFF + idx * 16, src + idx * 16);
        }
    }
    CP_COMMIT();

    for (int c = 0; c < NCHUNK; c++) {
        CP_WAIT0();   // B_c landed
        // ---- convert prefetched A regs -> smem
        {
            uint32_t hw[4], lw[4];
#pragma unroll
            for (int j = 0; j < 4; j++) hw[j] = pack_hi(v[2 * j], v[2 * j + 1], lw[j]);
            uint32_t off = sloc * 80 + kb * 16;
            *(uint4*)(smem_ + AHI_OFF + off) = make_uint4(hw[0], hw[1], hw[2], hw[3]);
            *(uint4*)(smem_ + ALO_OFF + off) = make_uint4(lw[0], lw[1], lw[2], lw[3]);
        }
        __syncthreads();

        // ---- prefetch chunk c+1 (overlaps the MMA phase)
        if (c < NCHUNK - 1) {
            const float* asrc = asrc0 + (size_t)(c + 1) * BK * S_TOT;
#pragma unroll
            for (int j = 0; j < 8; j++) v[j] = asrc[(size_t)j * S_TOT];
            const unsigned char* src = Wb + (size_t)(c + 1) * WPACK_PER;
            uint32_t dstb = sb + (((c + 1) & 1) ? B1_OFF : B0_OFF);
#pragma unroll
            for (int i = 0; i < 7; i++) {
                int idx = tid + i * 256;
                if (idx < 1600) cp_async16(dstb + idx * 16, src + idx * 16);
            }
            CP_COMMIT();
        }

        // ---- compute
        const uint32_t Bb = sb + ((c & 1) ? B1_OFF : B0_OFF);
#pragma unroll
        for (int ks = 0; ks < 2; ks++) {
            uint32_t aH[2][4], aL[2][4];
            const uint32_t arow = wm * 32 + (lane & 15);
            const uint32_t acol = ks * 32 + (lane >> 4) * 16;
#pragma unroll
            for (int mt = 0; mt < 2; mt++) {
                uint32_t addr = (arow + mt * 16) * 80 + acol;
                ldsm_x4(aH[mt], sb + AHI_OFF + addr);
                ldsm_x4(aL[mt], sb + ALO_OFF + addr);
            }
            const uint32_t brow0 = wn * 40 + (lane >> 4) * 8 + (lane & 7);
            const uint32_t bcol  = ks * 32 + ((lane >> 3) & 1) * 16;
#pragma unroll
            for (int p = 0; p < 2; p++) {   // n-tiles 0..3
                uint32_t bH[4], bL[4];
                uint32_t addr = (brow0 + p * 16) * 80 + bcol;
                ldsm_x4(bH, Bb + addr);
                ldsm_x4(bL, Bb + BLO_REL + addr);
#pragma unroll
                for (int h = 0; h < 2; h++) {
                    int nt = 2 * p + h;
#pragma unroll
                    for (int mt = 0; mt < 2; mt++) {
                        mma16816(acc[mt][nt], aH[mt], bH + 2 * h);
                        mma16816(acc[mt][nt], aL[mt], bH + 2 * h);
                        mma16816(acc[mt][nt], aH[mt], bL + 2 * h);
                    }
                }
            }
            {   // n-tile 4 (last 8 cols) via ldmatrix.x2
                uint32_t bH[2], bL[2];
                uint32_t addr = (wn * 40 + 32 + (lane & 7)) * 80
                              + ks * 32 + ((lane >> 3) & 1) * 16;
                ldsm_x2(bH, Bb + addr);
                ldsm_x2(bL, Bb + BLO_REL + addr);
#pragma unroll
                for (int mt = 0; mt < 2; mt++) {
                    mma16816(acc[mt][4], aH[mt], bH);
                    mma16816(acc[mt][4], aL[mt], bH);
                    mma16816(acc[mt][4], aH[mt], bL);
                }
            }
        }
        __syncthreads();   // A consumed; safe to overwrite next iter
    }

    // ---- epilogue: +bias, store y[co][s], per-co sum/sumsq atomics
    float* ybase = d_y[conv] + (size_t)n * COUT * S_TOT;
    const int statbase = conv * NB * COUT + n * COUT;
    const int r0 = s0 + wm * 32 + (lane >> 2);
#pragma unroll
    for (int nt = 0; nt < 5; nt++) {
        int co0 = wn * 40 + nt * 8 + 2 * (lane & 3);
        float b0 = bias[co0], b1 = bias[co0 + 1];
        float sA = 0.f, qA = 0.f, sB = 0.f, qB = 0.f;
#pragma unroll
        for (int mt = 0; mt < 2; mt++) {
            float c0 = acc[mt][nt][0] + b0;
            float c1 = acc[mt][nt][1] + b1;
            float c2 = acc[mt][nt][2] + b0;
            float c3 = acc[mt][nt][3] + b1;
            int r = r0 + mt * 16;
            ybase[(size_t)co0 * S_TOT + r]           = c0;
            ybase[(size_t)(co0 + 1) * S_TOT + r]     = c1;
            ybase[(size_t)co0 * S_TOT + r + 8]       = c2;
            ybase[(size_t)(co0 + 1) * S_TOT + r + 8] = c3;
            sA += c0 + c2; qA += c0 * c0 + c2 * c2;
            sB += c1 + c3; qB += c1 * c1 + c3 * c3;
        }
#pragma unroll
        for (int o = 4; o < 32; o <<= 1) {
            sA += __shfl_xor_sync(0xffffffffu, sA, o);
            qA += __shfl_xor_sync(0xffffffffu, qA, o);
            sB += __shfl_xor_sync(0xffffffffu, sB, o);
            qB += __shfl_xor_sync(0xffffffffu, qB, o);
        }
        if (lane < 4) {
            atomicAdd(&d_sum[statbase + co0], sA);
            atomicAdd(&d_sumsq[statbase + co0], qA);
            atomicAdd(&d_sum[statbase + co0 + 1], sB);
            atomicAdd(&d_sumsq[statbase + co0 + 1], qB);
        }
    }
}

// ---------------------------------------------------------------------------
__global__ void finalize_stats() {
    int i = blockIdx.x * blockDim.x + threadIdx.x;
    if (i < 2 * NB * COUT) {
        float m   = d_sum[i] * (1.f / (float)S_TOT);
        float var = d_sumsq[i] * (1.f / (float)S_TOT) - m * m;
        d_mu[i]   = m;
        d_istd[i] = rsqrtf(var + 1e-5f);
    }
}

// ---------------------------------------------------------------------------
// Fused: normalize, ELU, sum, Wpsi-dot, sigmoid, out = x*psi.  float2/thread.
__global__ __launch_bounds__(256)
void fuse_gate(const float* __restrict__ x, const float* __restrict__ Wpsi,
               const float* __restrict__ bpsi, float* __restrict__ out)
{
    __shared__ float smug[COUT], ssig[COUT], smux[COUT], ssix[COUT], sw[COUT];
    const int n = blockIdx.y, tid = threadIdx.x;
    if (tid < COUT) {
        smug[tid] = d_mu[n * COUT + tid];
        ssig[tid] = d_istd[n * COUT + tid];
        smux[tid] = d_mu[(NB + n) * COUT + tid];
        ssix[tid] = d_istd[(NB + n) * COUT + tid];
        sw[tid]   = Wpsi[tid];
    }
    __syncthreads();

    const size_t s  = ((size_t)blockIdx.x * 256 + tid) * 2;
    const float* yg = d_y[0] + (size_t)n * COUT * S_TOT + s;
    const float* yx = d_y[1] + (size_t)n * COUT * S_TOT + s;
    const float* xn = x      + (size_t)n * CIN  * S_TOT + s;
    float*       on = out    + (size_t)n * CIN  * S_TOT + s;

    float acc0 = bpsi[0], acc1 = acc0;
#pragma unroll 8
    for (int c = 0; c < COUT; c++) {
        float2 a2 = *(const float2*)(yg + (size_t)c * S_TOT);
        float2 b2 = *(const float2*)(yx + (size_t)c * S_TOT);
        float mg = smug[c], ig = ssig[c], mx = smux[c], ix = ssix[c], w = sw[c];
        float a0 = (a2.x - mg) * ig; a0 = a0 > 0.f ? a0 : (__expf(a0) - 1.f);
        float a1 = (a2.y - mg) * ig; a1 = a1 > 0.f ? a1 : (__expf(a1) - 1.f);
        float b0 = (b2.x - mx) * ix; b0 = b0 > 0.f ? b0 : (__expf(b0) - 1.f);
        float b1 = (b2.y - mx) * ix; b1 = b1 > 0.f ? b1 : (__expf(b1) - 1.f);
        acc0 = fmaf(w, a0 + b0, acc0);
        acc1 = fmaf(w, a1 + b1, acc1);
    }
    const float psi0 = 1.f / (1.f + __expf(-acc0));
    const float psi1 = 1.f / (1.f + __expf(-acc1));

#pragma unroll 8
    for (int c = 0; c < CIN; c++) {
        float2 xv = *(const float2*)(xn + (size_t)c * S_TOT);
        *(float2*)(on + (size_t)c * S_TOT) = make_float2(xv.x * psi0, xv.y * psi1);
    }
}

// ---------------------------------------------------------------------------
extern "C" void kernel_launch(void* const* d_in, const int* in_sizes, int n_in,
                              void* d_out, int out_size)
{
    const float* g    = (const float*)d_in[0];
    const float* x    = (const float*)d_in[1];
    const float* Wg   = (const float*)d_in[2];
    const float* bg   = (const float*)d_in[3];
    const float* Wx   = (const float*)d_in[4];
    const float* bx   = (const float*)d_in[5];
    const float* Wpsi = (const float*)d_in[6];
    const float* bpsi = (const float*)d_in[7];
    float* out = (float*)d_out;

    cudaFuncSetAttribute(gemm_mma, cudaFuncAttributeMaxDynamicSharedMemorySize, SMEM_BYTES);

    prepack_W<<<(2 * NCHUNK * COUT * 20 + 255) / 256, 256>>>(Wg, Wx);
    zero_stats<<<2, 512>>>();

    dim3 gg(S_TOT / BM, NB);   // (2048, 2)
    gemm_mma<<<gg, 256, SMEM_BYTES>>>(g, bg, 0);
    gemm_mma<<<gg, 256, SMEM_BYTES>>>(x, bx, 1);

    finalize_stats<<<2, 512>>>();

    dim3 gf(S_TOT / 512, NB);  // (256, 2)
    fuse_gate<<<gf, 256>>>(x, Wpsi, bpsi, out);
}